// round 1
// baseline (speedup 1.0000x reference)
#include <cuda_runtime.h>
#include <math.h>

// Problem constants
#define BB   4
#define TT   4096
#define CC   1024
#define HH   16
#define HDIM 64
#define NTOK (BB * TT)          // 16384
#define C3   (3 * CC)           // 3072

// GEMM tiling
#define BM 128
#define BN 128
#define BK 16
#define TM 8
#define TN 8

// Scratch (allocation-free rule: __device__ globals)
__device__ float g_qkv[(size_t)NTOK * C3];   // 201 MB
__device__ float g_y[(size_t)NTOK * CC];     //  67 MB

// ---------------------------------------------------------------------------
// C[M,N] = A[M,K] @ B[N,K]^T (+ bias[N]), all row-major fp32.
// 128x128 tile, BK=16, 256 threads, 8x8 accum/thread, float4 IO,
// LDG prefetch of next K-slab overlapped with smem compute.
// ---------------------------------------------------------------------------
__global__ __launch_bounds__(256) void sgemm_kernel(
    const float* __restrict__ A, const float* __restrict__ B,
    const float* __restrict__ bias, float* __restrict__ C,
    int M, int N, int K)
{
    __shared__ float As[BK][BM];
    __shared__ float Bs[BK][BN];

    const int tid = threadIdx.x;
    const int bm  = blockIdx.y * BM;
    const int bn  = blockIdx.x * BN;
    const int tr  = (tid >> 4) * TM;   // 0..120
    const int tc  = (tid & 15) * TN;   // 0..120

    // load mapping: 128 rows x 16 cols = 512 float4 => 2 per thread
    const int lr = tid >> 2;           // 0..63
    const int lc = (tid & 3) << 2;     // 0,4,8,12

    const float* Aptr = A + (size_t)(bm + lr) * K + lc;
    const float* Bptr = B + (size_t)(bn + lr) * K + lc;

    float acc[TM][TN];
    #pragma unroll
    for (int i = 0; i < TM; i++)
        #pragma unroll
        for (int j = 0; j < TN; j++) acc[i][j] = 0.0f;

    // prefetch first slab
    float4 a0 = *(const float4*)Aptr;
    float4 a1 = *(const float4*)(Aptr + (size_t)64 * K);
    float4 b0 = *(const float4*)Bptr;
    float4 b1 = *(const float4*)(Bptr + (size_t)64 * K);

    for (int k0 = 0; k0 < K; k0 += BK) {
        // regs -> smem (transposed: As[k][m], Bs[k][n])
        As[lc + 0][lr]      = a0.x; As[lc + 1][lr]      = a0.y;
        As[lc + 2][lr]      = a0.z; As[lc + 3][lr]      = a0.w;
        As[lc + 0][lr + 64] = a1.x; As[lc + 1][lr + 64] = a1.y;
        As[lc + 2][lr + 64] = a1.z; As[lc + 3][lr + 64] = a1.w;
        Bs[lc + 0][lr]      = b0.x; Bs[lc + 1][lr]      = b0.y;
        Bs[lc + 2][lr]      = b0.z; Bs[lc + 3][lr]      = b0.w;
        Bs[lc + 0][lr + 64] = b1.x; Bs[lc + 1][lr + 64] = b1.y;
        Bs[lc + 2][lr + 64] = b1.z; Bs[lc + 3][lr + 64] = b1.w;
        __syncthreads();

        // prefetch next slab (LDG latency hidden behind FFMA block below)
        if (k0 + BK < K) {
            Aptr += BK; Bptr += BK;
            a0 = *(const float4*)Aptr;
            a1 = *(const float4*)(Aptr + (size_t)64 * K);
            b0 = *(const float4*)Bptr;
            b1 = *(const float4*)(Bptr + (size_t)64 * K);
        }

        #pragma unroll
        for (int k = 0; k < BK; k++) {
            float ra[TM], rb[TN];
            #pragma unroll
            for (int i = 0; i < TM; i++) ra[i] = As[k][tr + i];
            #pragma unroll
            for (int j = 0; j < TN; j++) rb[j] = Bs[k][tc + j];
            #pragma unroll
            for (int i = 0; i < TM; i++)
                #pragma unroll
                for (int j = 0; j < TN; j++)
                    acc[i][j] = fmaf(ra[i], rb[j], acc[i][j]);
        }
        __syncthreads();
    }

    float rbias[TN];
    #pragma unroll
    for (int j = 0; j < TN; j++) rbias[j] = bias ? bias[bn + tc + j] : 0.0f;

    #pragma unroll
    for (int i = 0; i < TM; i++) {
        float4 v0, v1;
        v0.x = acc[i][0] + rbias[0]; v0.y = acc[i][1] + rbias[1];
        v0.z = acc[i][2] + rbias[2]; v0.w = acc[i][3] + rbias[3];
        v1.x = acc[i][4] + rbias[4]; v1.y = acc[i][5] + rbias[5];
        v1.z = acc[i][6] + rbias[6]; v1.w = acc[i][7] + rbias[7];
        float* cp = C + (size_t)(bm + tr + i) * N + bn + tc;
        *(float4*)cp       = v0;
        *(float4*)(cp + 4) = v1;
    }
}

// ---------------------------------------------------------------------------
// Per-token "attention over heads": for each token row of qkv (3072 floats,
// head h occupies [192h,192h+192) as q|k|v of 64 each):
//   S[h][g] = q_h . k_g / 8 ; softmax over g (16) ; out[h][d] = sum_g a*v_g[d]
// One CTA (256 thr) per token. Score loop uses d=(dd+g)&63 rotation so the
// 192-float head stride (== 0 mod 32 banks) doesn't cause 16-way conflicts.
// ---------------------------------------------------------------------------
__global__ __launch_bounds__(256) void attn_kernel(
    const float* __restrict__ qkv, float* __restrict__ y)
{
    __shared__ float sh[C3];
    __shared__ float att[16][16];

    const int token = blockIdx.x;
    const int tid   = threadIdx.x;
    const float* row = qkv + (size_t)token * C3;

    for (int i = tid; i < C3 / 4; i += 256)
        ((float4*)sh)[i] = ((const float4*)row)[i];
    __syncthreads();

    const int h = tid >> 4;       // 0..15
    const int g = tid & 15;       // 0..15
    const float* qp = sh + h * 192;
    const float* kp = sh + g * 192 + 64;

    float s = 0.0f;
    #pragma unroll
    for (int dd = 0; dd < 64; dd++) {
        int d = (dd + g) & 63;    // phase rotation -> conflict-free k reads
        s += qp[d] * kp[d];
    }
    att[h][g] = s * 0.125f;       // 1/sqrt(64)
    __syncthreads();

    // softmax over g, row h (each thread redundantly reduces its row: 16 reads)
    float m = -1e30f;
    #pragma unroll
    for (int j = 0; j < 16; j++) m = fmaxf(m, att[h][j]);
    float e = __expf(att[h][g] - m);
    __syncthreads();
    att[h][g] = e;                // store unnormalized exp
    __syncthreads();
    float denom = 0.0f;
    #pragma unroll
    for (int j = 0; j < 16; j++) denom += att[h][j];
    const float inv = 1.0f / denom;   // this thread's row h == output row below

    // out[h][d0..d0+3] = inv * sum_g e[h][g] * v[g][d]
    const int d0 = (tid & 15) * 4;
    float4 o = make_float4(0.f, 0.f, 0.f, 0.f);
    #pragma unroll
    for (int g2 = 0; g2 < 16; g2++) {
        const float w = att[h][g2];
        const float* vp = sh + g2 * 192 + 128 + d0;
        o.x += w * vp[0];
        o.y += w * vp[1];
        o.z += w * vp[2];
        o.w += w * vp[3];
    }
    o.x *= inv; o.y *= inv; o.z *= inv; o.w *= inv;
    *(float4*)(y + (size_t)token * CC + h * HDIM + d0) = o;
}

// ---------------------------------------------------------------------------
extern "C" void kernel_launch(void* const* d_in, const int* in_sizes, int n_in,
                              void* d_out, int out_size)
{
    const float* x    = (const float*)d_in[0];   // (B,T,C)
    const float* Wqkv = (const float*)d_in[1];   // (3C,C)
    const float* Wout = (const float*)d_in[2];   // (C,C)
    const float* bout = (const float*)d_in[3];   // (C,)
    float* out = (float*)d_out;                  // (B,T,C) fp32

    float *qkv = nullptr, *y = nullptr;
    cudaGetSymbolAddress((void**)&qkv, g_qkv);
    cudaGetSymbolAddress((void**)&y,   g_y);

    dim3 blk(256);

    // GEMM1: qkv = x @ Wqkv^T   (16384 x 3072, K=1024)
    dim3 g1(C3 / BN, NTOK / BM);
    sgemm_kernel<<<g1, blk>>>(x, Wqkv, nullptr, qkv, NTOK, C3, CC);

    // per-token head-attention
    attn_kernel<<<NTOK, 256>>>(qkv, y);

    // GEMM2: out = y @ Wout^T + bout   (16384 x 1024, K=1024)
    dim3 g2(CC / BN, NTOK / BM);
    sgemm_kernel<<<g2, blk>>>(y, Wout, bout, out, NTOK, CC, CC);
}

// round 3
// speedup vs baseline: 1.9738x; 1.9738x over previous
#include <cuda_runtime.h>
#include <cuda_bf16.h>
#include <stdint.h>
#include <math.h>

// ---------------- problem constants ----------------
#define BBATCH 4
#define TSEQ   4096
#define CDIM   1024
#define HH     16
#define HDIM   64
#define NTOK   (BBATCH * TSEQ)   // 16384
#define C3     (3 * CDIM)        // 3072

// ---------------- scratch (allocation-free rule) ----------------
__device__ float          g_qkv[(size_t)NTOK * C3];      // 201 MB fp32
__device__ float          g_y  [(size_t)NTOK * CDIM];    //  67 MB fp32
__device__ __nv_bfloat16  g_xhi[(size_t)NTOK * CDIM];
__device__ __nv_bfloat16  g_xlo[(size_t)NTOK * CDIM];
__device__ __nv_bfloat16  g_yhi[(size_t)NTOK * CDIM];
__device__ __nv_bfloat16  g_ylo[(size_t)NTOK * CDIM];
__device__ __nv_bfloat16  g_w1hi[(size_t)C3 * CDIM];
__device__ __nv_bfloat16  g_w1lo[(size_t)C3 * CDIM];
__device__ __nv_bfloat16  g_w2hi[(size_t)CDIM * CDIM];
__device__ __nv_bfloat16  g_w2lo[(size_t)CDIM * CDIM];

// ---------------- PTX helpers (baseline sm_80+ features only) ----------------
__device__ __forceinline__ uint32_t smem_u32(const void* p) {
    uint32_t a;
    asm("{ .reg .u64 t; cvta.to.shared.u64 t, %1; cvt.u32.u64 %0, t; }"
        : "=r"(a) : "l"(p));
    return a;
}

#define CP_ASYNC16(dst_u32, src_ptr) \
    asm volatile("cp.async.cg.shared.global [%0], [%1], 16;" \
                 :: "r"(dst_u32), "l"(src_ptr) : "memory")
#define CP_COMMIT() asm volatile("cp.async.commit_group;" ::: "memory")
#define CP_WAIT(n)  asm volatile("cp.async.wait_group %0;" :: "n"(n) : "memory")

#define LDSM4(r, addr) \
    asm volatile("ldmatrix.sync.aligned.m8n8.x4.shared.b16 {%0,%1,%2,%3}, [%4];" \
        : "=r"((r)[0]), "=r"((r)[1]), "=r"((r)[2]), "=r"((r)[3]) : "r"(addr))

#define MMA16816(d, a, b0, b1) \
    asm volatile("mma.sync.aligned.m16n8k16.row.col.f32.bf16.bf16.f32 " \
        "{%0,%1,%2,%3}, {%4,%5,%6,%7}, {%8,%9}, {%0,%1,%2,%3};" \
        : "+f"((d)[0]), "+f"((d)[1]), "+f"((d)[2]), "+f"((d)[3]) \
        : "r"((a)[0]), "r"((a)[1]), "r"((a)[2]), "r"((a)[3]), "r"(b0), "r"(b1))

// ---------------- smem geometry ----------------
// Tiles stored with row pitch 80 B (32 bf16 data + 8 pad) -> conflict-free
// ldmatrix (8 rows @ 20-word stride hit all 32 banks once).
#define PITCH_B   80
#define TILE_B    (128 * PITCH_B)        // 10240 B per tile
#define STAGE_B   (4 * TILE_B)           // Ahi,Alo,Bhi,Blo = 40960 B
#define SMEM_B    (2 * STAGE_B)          // double buffered = 81920 B
#define OFF_AHI   0
#define OFF_ALO   TILE_B
#define OFF_BHI   (2 * TILE_B)
#define OFF_BLO   (3 * TILE_B)
#define BKC       32                      // K per chunk

// ---------------------------------------------------------------------------
// C[M,N] = (Ahi+Alo)[M,K] @ (Bhi+Blo)[N,K]^T (+bias), bf16 split, HMMA.
// 128x128 CTA tile, 256 thr, warp tile 64x32, cp.async double buffer.
// ---------------------------------------------------------------------------
__global__ __launch_bounds__(256) void hmma_gemm(
    const __nv_bfloat16* __restrict__ Ahi, const __nv_bfloat16* __restrict__ Alo,
    const __nv_bfloat16* __restrict__ Bhi, const __nv_bfloat16* __restrict__ Blo,
    const float* __restrict__ bias, float* __restrict__ C,
    int M, int N, int K)
{
    extern __shared__ char sm[];
    const uint32_t sbase = smem_u32(sm);

    const int tid  = threadIdx.x;
    const int lane = tid & 31;
    const int wid  = tid >> 5;
    const int wm   = wid & 1;        // M half (0..1)
    const int wn   = wid >> 1;       // N quarter (0..3)
    const int bm   = blockIdx.y * 128;
    const int bn   = blockIdx.x * 128;

    // ---- loader mapping: 128 rows x 4 chunks(16B); 2 chunks per thread ----
    const int lr = tid >> 1;              // 0..127
    const int lc = (tid & 1) * 2;         // 0 or 2
    const __nv_bfloat16* gAh = Ahi + (size_t)(bm + lr) * K + lc * 8;
    const __nv_bfloat16* gAl = Alo + (size_t)(bm + lr) * K + lc * 8;
    const __nv_bfloat16* gBh = Bhi + (size_t)(bn + lr) * K + lc * 8;
    const __nv_bfloat16* gBl = Blo + (size_t)(bn + lr) * K + lc * 8;
    const uint32_t sRow = (uint32_t)(lr * PITCH_B + lc * 16);

    // ---- fragment smem addresses (lane-dependent pieces) ----
    // addr = tile_base + (atomRow + (lane&15))*80 + (lane>>4)*16 (+ s*32 per k16)
    const uint32_t aOff = (uint32_t)((wm * 64 + (lane & 15)) * PITCH_B + (lane >> 4) * 16);
    const uint32_t bOff = (uint32_t)((wn * 32 + (lane & 15)) * PITCH_B + (lane >> 4) * 16);

    float acc[4][4][4];
    #pragma unroll
    for (int i = 0; i < 4; i++)
        #pragma unroll
        for (int j = 0; j < 4; j++)
            #pragma unroll
            for (int q = 0; q < 4; q++) acc[i][j][q] = 0.0f;

    const int KC = K / BKC;

    // ---- prologue: load chunk 0 into stage 0 ----
    {
        const uint32_t st = sbase + sRow;
        CP_ASYNC16(st + OFF_AHI,      gAh);
        CP_ASYNC16(st + OFF_AHI + 16, gAh + 8);
        CP_ASYNC16(st + OFF_ALO,      gAl);
        CP_ASYNC16(st + OFF_ALO + 16, gAl + 8);
        CP_ASYNC16(st + OFF_BHI,      gBh);
        CP_ASYNC16(st + OFF_BHI + 16, gBh + 8);
        CP_ASYNC16(st + OFF_BLO,      gBl);
        CP_ASYNC16(st + OFF_BLO + 16, gBl + 8);
        CP_COMMIT();
    }

    for (int c = 0; c < KC; c++) {
        const uint32_t cur = sbase + (uint32_t)((c & 1) * STAGE_B);

        // prefetch chunk c+1 into the other stage
        if (c + 1 < KC) {
            const uint32_t nxt = sbase + (uint32_t)(((c + 1) & 1) * STAGE_B) + sRow;
            const int ko = (c + 1) * BKC;
            CP_ASYNC16(nxt + OFF_AHI,      gAh + ko);
            CP_ASYNC16(nxt + OFF_AHI + 16, gAh + ko + 8);
            CP_ASYNC16(nxt + OFF_ALO,      gAl + ko);
            CP_ASYNC16(nxt + OFF_ALO + 16, gAl + ko + 8);
            CP_ASYNC16(nxt + OFF_BHI,      gBh + ko);
            CP_ASYNC16(nxt + OFF_BHI + 16, gBh + ko + 8);
            CP_ASYNC16(nxt + OFF_BLO,      gBl + ko);
            CP_ASYNC16(nxt + OFF_BLO + 16, gBl + ko + 8);
            CP_COMMIT();
            CP_WAIT(1);              // chunk c resident
        } else {
            CP_WAIT(0);
        }
        __syncthreads();

        #pragma unroll
        for (int s = 0; s < 2; s++) {        // two k16 steps per chunk
            const uint32_t ks = (uint32_t)(s * 32);
            uint32_t ah[4][4], al[4][4], bh[2][4], bl[2][4];
            #pragma unroll
            for (int i = 0; i < 4; i++) {
                LDSM4(ah[i], cur + OFF_AHI + aOff + ks + (uint32_t)(i * 16 * PITCH_B));
                LDSM4(al[i], cur + OFF_ALO + aOff + ks + (uint32_t)(i * 16 * PITCH_B));
            }
            #pragma unroll
            for (int nb = 0; nb < 2; nb++) {
                LDSM4(bh[nb], cur + OFF_BHI + bOff + ks + (uint32_t)(nb * 16 * PITCH_B));
                LDSM4(bl[nb], cur + OFF_BLO + bOff + ks + (uint32_t)(nb * 16 * PITCH_B));
            }
            #pragma unroll
            for (int i = 0; i < 4; i++) {
                #pragma unroll
                for (int j = 0; j < 4; j++) {
                    const int nb = j >> 1;
                    const int jj = j & 1;
                    const uint32_t bh0 = jj ? bh[nb][1] : bh[nb][0];
                    const uint32_t bh1 = jj ? bh[nb][3] : bh[nb][2];
                    const uint32_t bl0 = jj ? bl[nb][1] : bl[nb][0];
                    const uint32_t bl1 = jj ? bl[nb][3] : bl[nb][2];
                    MMA16816(acc[i][j], ah[i], bh0, bh1);   // hi*hi
                    MMA16816(acc[i][j], ah[i], bl0, bl1);   // hi*lo
                    MMA16816(acc[i][j], al[i], bh0, bh1);   // lo*hi
                }
            }
        }
        __syncthreads();
    }

    // ---- epilogue: d-frag -> global (float2 stores), fused bias ----
    #pragma unroll
    for (int i = 0; i < 4; i++) {
        const int row = bm + wm * 64 + i * 16 + (lane >> 2);
        #pragma unroll
        for (int j = 0; j < 4; j++) {
            const int col = bn + wn * 32 + j * 8 + (lane & 3) * 2;
            float b0 = 0.f, b1 = 0.f;
            if (bias) { b0 = bias[col]; b1 = bias[col + 1]; }
            float2 v0 = make_float2(acc[i][j][0] + b0, acc[i][j][1] + b1);
            float2 v1 = make_float2(acc[i][j][2] + b0, acc[i][j][3] + b1);
            *(float2*)(C + (size_t)row * N + col)        = v0;
            *(float2*)(C + (size_t)(row + 8) * N + col)  = v1;
        }
    }
}

// ---------------------------------------------------------------------------
// fp32 -> bf16 hi/lo split
// ---------------------------------------------------------------------------
__global__ __launch_bounds__(256) void split_kernel(
    const float* __restrict__ src, __nv_bfloat16* __restrict__ hi,
    __nv_bfloat16* __restrict__ lo, int n4)
{
    const int i = blockIdx.x * blockDim.x + threadIdx.x;
    if (i >= n4) return;
    const float4 v = ((const float4*)src)[i];
    __nv_bfloat16 h0 = __float2bfloat16_rn(v.x);
    __nv_bfloat16 h1 = __float2bfloat16_rn(v.y);
    __nv_bfloat16 h2 = __float2bfloat16_rn(v.z);
    __nv_bfloat16 h3 = __float2bfloat16_rn(v.w);
    __nv_bfloat16 l0 = __float2bfloat16_rn(v.x - __bfloat162float(h0));
    __nv_bfloat16 l1 = __float2bfloat16_rn(v.y - __bfloat162float(h1));
    __nv_bfloat16 l2 = __float2bfloat16_rn(v.z - __bfloat162float(h2));
    __nv_bfloat16 l3 = __float2bfloat16_rn(v.w - __bfloat162float(h3));
    __nv_bfloat162* hp = (__nv_bfloat162*)(hi + (size_t)i * 4);
    __nv_bfloat162* lp = (__nv_bfloat162*)(lo + (size_t)i * 4);
    hp[0] = __nv_bfloat162(h0, h1);
    hp[1] = __nv_bfloat162(h2, h3);
    lp[0] = __nv_bfloat162(l0, l1);
    lp[1] = __nv_bfloat162(l2, l3);
}

// ---------------------------------------------------------------------------
// Per-token attention over heads (fp32) — verified in round 1.
// ---------------------------------------------------------------------------
__global__ __launch_bounds__(256) void attn_kernel(
    const float* __restrict__ qkv, float* __restrict__ y)
{
    __shared__ float sh[C3];
    __shared__ float att[16][16];

    const int token = blockIdx.x;
    const int tid   = threadIdx.x;
    const float* row = qkv + (size_t)token * C3;

    for (int i = tid; i < C3 / 4; i += 256)
        ((float4*)sh)[i] = ((const float4*)row)[i];
    __syncthreads();

    const int h = tid >> 4;
    const int g = tid & 15;
    const float* qp = sh + h * 192;
    const float* kp = sh + g * 192 + 64;

    float s = 0.0f;
    #pragma unroll
    for (int dd = 0; dd < 64; dd++) {
        int d = (dd + g) & 63;
        s += qp[d] * kp[d];
    }
    att[h][g] = s * 0.125f;
    __syncthreads();

    float m = -1e30f;
    #pragma unroll
    for (int j = 0; j < 16; j++) m = fmaxf(m, att[h][j]);
    float e = __expf(att[h][g] - m);
    __syncthreads();
    att[h][g] = e;
    __syncthreads();
    float denom = 0.0f;
    #pragma unroll
    for (int j = 0; j < 16; j++) denom += att[h][j];
    const float inv = 1.0f / denom;

    const int d0 = (tid & 15) * 4;
    float4 o = make_float4(0.f, 0.f, 0.f, 0.f);
    #pragma unroll
    for (int g2 = 0; g2 < 16; g2++) {
        const float w = att[h][g2];
        const float* vp = sh + g2 * 192 + 128 + d0;
        o.x += w * vp[0];
        o.y += w * vp[1];
        o.z += w * vp[2];
        o.w += w * vp[3];
    }
    o.x *= inv; o.y *= inv; o.z *= inv; o.w *= inv;
    *(float4*)(y + (size_t)token * CDIM + h * HDIM + d0) = o;
}

// ---------------------------------------------------------------------------
extern "C" void kernel_launch(void* const* d_in, const int* in_sizes, int n_in,
                              void* d_out, int out_size)
{
    const float* x    = (const float*)d_in[0];
    const float* Wqkv = (const float*)d_in[1];
    const float* Wout = (const float*)d_in[2];
    const float* bout = (const float*)d_in[3];
    float* out = (float*)d_out;

    float *qkv, *y;
    __nv_bfloat16 *xhi, *xlo, *yhi, *ylo, *w1hi, *w1lo, *w2hi, *w2lo;
    cudaGetSymbolAddress((void**)&qkv,  g_qkv);
    cudaGetSymbolAddress((void**)&y,    g_y);
    cudaGetSymbolAddress((void**)&xhi,  g_xhi);
    cudaGetSymbolAddress((void**)&xlo,  g_xlo);
    cudaGetSymbolAddress((void**)&yhi,  g_yhi);
    cudaGetSymbolAddress((void**)&ylo,  g_ylo);
    cudaGetSymbolAddress((void**)&w1hi, g_w1hi);
    cudaGetSymbolAddress((void**)&w1lo, g_w1lo);
    cudaGetSymbolAddress((void**)&w2hi, g_w2hi);
    cudaGetSymbolAddress((void**)&w2lo, g_w2lo);

    cudaFuncSetAttribute(hmma_gemm, cudaFuncAttributeMaxDynamicSharedMemorySize, SMEM_B);

    // splits
    split_kernel<<<(NTOK * CDIM / 4 + 255) / 256, 256>>>(x, xhi, xlo, NTOK * CDIM / 4);
    split_kernel<<<(C3 * CDIM / 4 + 255) / 256, 256>>>(Wqkv, w1hi, w1lo, C3 * CDIM / 4);
    split_kernel<<<(CDIM * CDIM / 4 + 255) / 256, 256>>>(Wout, w2hi, w2lo, CDIM * CDIM / 4);

    // GEMM1: qkv = x @ Wqkv^T   (16384 x 3072, K=1024)
    hmma_gemm<<<dim3(C3 / 128, NTOK / 128), 256, SMEM_B>>>(
        xhi, xlo, w1hi, w1lo, nullptr, qkv, NTOK, C3, CDIM);

    // attention over heads
    attn_kernel<<<NTOK, 256>>>(qkv, y);

    // split y
    split_kernel<<<(NTOK * CDIM / 4 + 255) / 256, 256>>>(y, yhi, ylo, NTOK * CDIM / 4);

    // GEMM2: out = y @ Wout^T + bout   (16384 x 1024, K=1024)
    hmma_gemm<<<dim3(CDIM / 128, NTOK / 128), 256, SMEM_B>>>(
        yhi, ylo, w2hi, w2lo, bout, out, NTOK, CDIM, CDIM);
}

// round 4
// speedup vs baseline: 2.3756x; 1.2036x over previous
#include <cuda_runtime.h>
#include <stdint.h>
#include <math.h>

// ---------------- problem constants ----------------
#define CDIM   1024
#define NTOK   16384             // B*T = 4*4096
#define C3     (3 * CDIM)        // 3072

// ---------------- scratch (allocation-free rule) ----------------
__device__ float g_qkv[(size_t)NTOK * C3];    // 201 MB
__device__ float g_y  [(size_t)NTOK * CDIM];  //  67 MB (tf32-rounded by attn)
__device__ float g_xt [(size_t)NTOK * CDIM];  //  67 MB (tf32-rounded x)
__device__ float g_w1t[(size_t)C3 * CDIM];    //  12.6 MB
__device__ float g_w2t[(size_t)CDIM * CDIM];  //   4.2 MB

// ---------------- PTX helpers (baseline sm_80+ only) ----------------
__device__ __forceinline__ uint32_t smem_u32(const void* p) {
    uint32_t a;
    asm("{ .reg .u64 t; cvta.to.shared.u64 t, %1; cvt.u32.u64 %0, t; }"
        : "=r"(a) : "l"(p));
    return a;
}

#define CP_ASYNC16(dst_u32, src_ptr) \
    asm volatile("cp.async.cg.shared.global [%0], [%1], 16;" \
                 :: "r"(dst_u32), "l"(src_ptr) : "memory")
#define CP_COMMIT() asm volatile("cp.async.commit_group;" ::: "memory")
#define CP_WAIT(n)  asm volatile("cp.async.wait_group %0;" :: "n"(n) : "memory")

#define LDSM4(r, addr) \
    asm volatile("ldmatrix.sync.aligned.m8n8.x4.shared.b16 {%0,%1,%2,%3}, [%4];" \
        : "=r"((r)[0]), "=r"((r)[1]), "=r"((r)[2]), "=r"((r)[3]) : "r"(addr))

// m16n8k8 tf32: A = 4 regs, B = 2 regs, fp32 accumulate
#define MMA_TF32(d, a, b0, b1) \
    asm volatile("mma.sync.aligned.m16n8k8.row.col.f32.tf32.tf32.f32 " \
        "{%0,%1,%2,%3}, {%4,%5,%6,%7}, {%8,%9}, {%0,%1,%2,%3};" \
        : "+f"((d)[0]), "+f"((d)[1]), "+f"((d)[2]), "+f"((d)[3]) \
        : "r"((a)[0]), "r"((a)[1]), "r"((a)[2]), "r"((a)[3]), "r"(b0), "r"(b1))

__device__ __forceinline__ uint32_t f2tf32(float x) {
    uint32_t r;
    asm("cvt.rna.tf32.f32 %0, %1;" : "=r"(r) : "f"(x));
    return r;
}

// ---------------- smem geometry ----------------
// fp32 tiles, row pitch 144 B (32 floats + 16 B pad): ldmatrix phases are
// 8 rows @ 36-word stride -> banks 4r mod 32, conflict-free.
#define PITCH   144
#define TILE_B  (128 * PITCH)      // 18432 B
#define OFF_B   TILE_B             // B tile after A tile
#define STAGE_B (2 * TILE_B)       // 36864 B
#define NSTG    3
#define SMEM_B  (NSTG * STAGE_B)   // 110592 B
#define BKC     32                 // K per chunk (4 k8 steps)

// ---------------------------------------------------------------------------
// C[M,N] = A[M,K] @ B[N,K]^T (+bias); A,B fp32 already tf32-rounded.
// 128x128 CTA tile, 8 warps (64x32 each), 3-stage cp.async, TF32 HMMA.
// ---------------------------------------------------------------------------
__global__ __launch_bounds__(256) void tf32_gemm(
    const float* __restrict__ A, const float* __restrict__ B,
    const float* __restrict__ bias, float* __restrict__ C,
    int M, int N, int K)
{
    extern __shared__ char sm[];
    const uint32_t sbase = smem_u32(sm);

    const int tid  = threadIdx.x;
    const int lane = tid & 31;
    const int wid  = tid >> 5;
    const int wm   = wid & 1;       // M half
    const int wn   = wid >> 1;      // N quarter
    const int bm   = blockIdx.y * 128;
    const int bn   = blockIdx.x * 128;

    // ---- loader mapping: 128 rows x 2 half-rows(64B) per tile ----
    const int lr   = tid >> 1;          // 0..127
    const int lh   = tid & 1;           // 0/1
    const float* gA = A + (size_t)(bm + lr) * K + lh * 16;
    const float* gB = B + (size_t)(bn + lr) * K + lh * 16;
    const uint32_t sRow = (uint32_t)(lr * PITCH + lh * 64);

    // ---- ldmatrix lane addressing ----
    // A x4 tiles: (r0..7,k0..3)(r8..15,k0..3)(r0..7,k4..7)(r8..15,k4..7)
    // B x4 tiles: (n0..7,k0..3)(n0..7,k4..7)(n8..15,k0..3)(n8..15,k4..7)
    const int g  = lane >> 3;
    const int l8 = lane & 7;
    const uint32_t aLane = (uint32_t)((wm * 64 + l8 + (g & 1) * 8) * PITCH + (g >> 1) * 16);
    const uint32_t bLane = (uint32_t)((wn * 32 + l8 + (g >> 1) * 8) * PITCH + (g & 1) * 16);

    float acc[4][4][4];
    #pragma unroll
    for (int i = 0; i < 4; i++)
        #pragma unroll
        for (int j = 0; j < 4; j++)
            #pragma unroll
            for (int q = 0; q < 4; q++) acc[i][j][q] = 0.0f;

    const int KC = K / BKC;

    // issue one stage's cp.async copies (A + B, 8x16B per thread)
    auto issue = [&](int stg, int ko) {
        const uint32_t dA = sbase + (uint32_t)stg * STAGE_B + sRow;
        const uint32_t dB = dA + OFF_B;
        const float* sa = gA + ko;
        const float* sb = gB + ko;
        #pragma unroll
        for (int j = 0; j < 4; j++) {
            CP_ASYNC16(dA + j * 16, sa + j * 4);
            CP_ASYNC16(dB + j * 16, sb + j * 4);
        }
    };

    // prologue: 2 stages in flight
    issue(0, 0);  CP_COMMIT();
    issue(1, BKC); CP_COMMIT();

    uint32_t af[2][4][4], bf[2][2][4];

    for (int c = 0; c < KC; c++) {
        if (c == KC - 1) { CP_WAIT(0); } else { CP_WAIT(1); }
        __syncthreads();
        if (c + 2 < KC) { issue((c + 2) % NSTG, (c + 2) * BKC); CP_COMMIT(); }

        const uint32_t stg = sbase + (uint32_t)(c % NSTG) * STAGE_B;
        const uint32_t aB  = stg + aLane;
        const uint32_t bB  = stg + OFF_B + bLane;

        // load frags for k8-step 0
        #pragma unroll
        for (int i = 0; i < 4; i++) LDSM4(af[0][i], aB + (uint32_t)(i * 16 * PITCH));
        #pragma unroll
        for (int p = 0; p < 2; p++) LDSM4(bf[0][p], bB + (uint32_t)(p * 16 * PITCH));

        #pragma unroll
        for (int s = 0; s < 4; s++) {
            const int cur = s & 1;
            if (s < 3) {               // prefetch frags for step s+1
                const uint32_t ks = (uint32_t)((s + 1) * 32);
                const int nxt = cur ^ 1;
                #pragma unroll
                for (int i = 0; i < 4; i++)
                    LDSM4(af[nxt][i], aB + ks + (uint32_t)(i * 16 * PITCH));
                #pragma unroll
                for (int p = 0; p < 2; p++)
                    LDSM4(bf[nxt][p], bB + ks + (uint32_t)(p * 16 * PITCH));
            }
            #pragma unroll
            for (int i = 0; i < 4; i++) {
                #pragma unroll
                for (int j = 0; j < 4; j++) {
                    const int p = j >> 1, q = j & 1;
                    MMA_TF32(acc[i][j], af[cur][i], bf[cur][p][q * 2], bf[cur][p][q * 2 + 1]);
                }
            }
        }
    }

    // ---- epilogue ----
    #pragma unroll
    for (int i = 0; i < 4; i++) {
        const int row = bm + wm * 64 + i * 16 + (lane >> 2);
        #pragma unroll
        for (int j = 0; j < 4; j++) {
            const int col = bn + wn * 32 + j * 8 + (lane & 3) * 2;
            float b0 = 0.f, b1 = 0.f;
            if (bias) { b0 = bias[col]; b1 = bias[col + 1]; }
            float2 v0 = make_float2(acc[i][j][0] + b0, acc[i][j][1] + b1);
            float2 v1 = make_float2(acc[i][j][2] + b0, acc[i][j][3] + b1);
            *(float2*)(C + (size_t)row * N + col)       = v0;
            *(float2*)(C + (size_t)(row + 8) * N + col) = v1;
        }
    }
}

// ---------------------------------------------------------------------------
// fp32 -> tf32-rounded fp32 (cvt.rna), vectorized
// ---------------------------------------------------------------------------
__global__ __launch_bounds__(256) void round_tf32_kernel(
    const float* __restrict__ src, float* __restrict__ dst, int n4)
{
    const int i = blockIdx.x * blockDim.x + threadIdx.x;
    if (i >= n4) return;
    const float4 v = ((const float4*)src)[i];
    uint4 r;
    r.x = f2tf32(v.x); r.y = f2tf32(v.y);
    r.z = f2tf32(v.z); r.w = f2tf32(v.w);
    ((uint4*)dst)[i] = r;
}

// ---------------------------------------------------------------------------
// Per-token attention over heads (fp32), outputs tf32-rounded y.
// ---------------------------------------------------------------------------
__global__ __launch_bounds__(256) void attn_kernel(
    const float* __restrict__ qkv, float* __restrict__ y)
{
    __shared__ float sh[C3];
    __shared__ float att[16][16];

    const int token = blockIdx.x;
    const int tid   = threadIdx.x;
    const float* row = qkv + (size_t)token * C3;

    for (int i = tid; i < C3 / 4; i += 256)
        ((float4*)sh)[i] = ((const float4*)row)[i];
    __syncthreads();

    const int h = tid >> 4;
    const int gg = tid & 15;
    const float* qp = sh + h * 192;
    const float* kp = sh + gg * 192 + 64;

    float s = 0.0f;
    #pragma unroll
    for (int dd = 0; dd < 64; dd++) {
        int d = (dd + gg) & 63;
        s += qp[d] * kp[d];
    }
    att[h][gg] = s * 0.125f;
    __syncthreads();

    float m = -1e30f;
    #pragma unroll
    for (int j = 0; j < 16; j++) m = fmaxf(m, att[h][j]);
    float e = __expf(att[h][gg] - m);
    __syncthreads();
    att[h][gg] = e;
    __syncthreads();
    float denom = 0.0f;
    #pragma unroll
    for (int j = 0; j < 16; j++) denom += att[h][j];
    const float inv = 1.0f / denom;

    const int d0 = (tid & 15) * 4;
    float4 o = make_float4(0.f, 0.f, 0.f, 0.f);
    #pragma unroll
    for (int g2 = 0; g2 < 16; g2++) {
        const float w = att[h][g2];
        const float* vp = sh + g2 * 192 + 128 + d0;
        o.x += w * vp[0];
        o.y += w * vp[1];
        o.z += w * vp[2];
        o.w += w * vp[3];
    }
    uint4 r;
    r.x = f2tf32(o.x * inv);
    r.y = f2tf32(o.y * inv);
    r.z = f2tf32(o.z * inv);
    r.w = f2tf32(o.w * inv);
    *(uint4*)(y + (size_t)token * CDIM + h * 64 + d0) = r;
}

// ---------------------------------------------------------------------------
extern "C" void kernel_launch(void* const* d_in, const int* in_sizes, int n_in,
                              void* d_out, int out_size)
{
    const float* x    = (const float*)d_in[0];
    const float* Wqkv = (const float*)d_in[1];
    const float* Wout = (const float*)d_in[2];
    const float* bout = (const float*)d_in[3];
    float* out = (float*)d_out;

    float *qkv, *y, *xt, *w1t, *w2t;
    cudaGetSymbolAddress((void**)&qkv, g_qkv);
    cudaGetSymbolAddress((void**)&y,   g_y);
    cudaGetSymbolAddress((void**)&xt,  g_xt);
    cudaGetSymbolAddress((void**)&w1t, g_w1t);
    cudaGetSymbolAddress((void**)&w2t, g_w2t);

    cudaFuncSetAttribute(tf32_gemm, cudaFuncAttributeMaxDynamicSharedMemorySize, SMEM_B);

    // tf32 rounding passes (rna: unbiased-ish, required for accuracy)
    round_tf32_kernel<<<(NTOK * CDIM / 4 + 255) / 256, 256>>>(x, xt, NTOK * CDIM / 4);
    round_tf32_kernel<<<(C3 * CDIM / 4 + 255) / 256, 256>>>(Wqkv, w1t, C3 * CDIM / 4);
    round_tf32_kernel<<<(CDIM * CDIM / 4 + 255) / 256, 256>>>(Wout, w2t, CDIM * CDIM / 4);

    // GEMM1: qkv = xt @ w1t^T   (16384 x 3072, K=1024)
    tf32_gemm<<<dim3(C3 / 128, NTOK / 128), 256, SMEM_B>>>(
        xt, w1t, nullptr, qkv, NTOK, C3, CDIM);

    // attention over heads (emits tf32-rounded y)
    attn_kernel<<<NTOK, 256>>>(qkv, y);

    // GEMM2: out = y @ w2t^T + bout   (16384 x 1024, K=1024)
    tf32_gemm<<<dim3(CDIM / 128, NTOK / 128), 256, SMEM_B>>>(
        y, w2t, bout, out, NTOK, CDIM, CDIM);
}

// round 5
// speedup vs baseline: 3.0003x; 1.2629x over previous
#include <cuda_runtime.h>
#include <stdint.h>
#include <math.h>

// ---------------- problem constants ----------------
#define CDIM   1024
#define NTOK   16384             // B*T = 4*4096
#define C3     (3 * CDIM)        // 3072

// ---------------- scratch (allocation-free rule) ----------------
__device__ float g_qkv[(size_t)NTOK * C3];    // 201 MB
__device__ float g_y  [(size_t)NTOK * CDIM];  //  67 MB (tf32-rounded by attn)
__device__ float g_xt [(size_t)NTOK * CDIM];  //  67 MB (tf32-rounded x)
__device__ float g_w1t[(size_t)C3 * CDIM];
__device__ float g_w2t[(size_t)CDIM * CDIM];

// ---------------- PTX helpers (baseline sm_80+ only) ----------------
__device__ __forceinline__ uint32_t smem_u32(const void* p) {
    uint32_t a;
    asm("{ .reg .u64 t; cvta.to.shared.u64 t, %1; cvt.u32.u64 %0, t; }"
        : "=r"(a) : "l"(p));
    return a;
}

#define CP_ASYNC16(dst_u32, src_ptr) \
    asm volatile("cp.async.cg.shared.global [%0], [%1], 16;" \
                 :: "r"(dst_u32), "l"(src_ptr) : "memory")
#define CP_COMMIT() asm volatile("cp.async.commit_group;" ::: "memory")
#define CP_WAIT(n)  asm volatile("cp.async.wait_group %0;" :: "n"(n) : "memory")

#define LDSM4(r, addr) \
    asm volatile("ldmatrix.sync.aligned.m8n8.x4.shared.b16 {%0,%1,%2,%3}, [%4];" \
        : "=r"((r)[0]), "=r"((r)[1]), "=r"((r)[2]), "=r"((r)[3]) : "r"(addr))

// m16n8k8 tf32: A = 4 regs, B = 2 regs, fp32 accumulate
#define MMA_TF32(d, a, b0, b1) \
    asm volatile("mma.sync.aligned.m16n8k8.row.col.f32.tf32.tf32.f32 " \
        "{%0,%1,%2,%3}, {%4,%5,%6,%7}, {%8,%9}, {%0,%1,%2,%3};" \
        : "+f"((d)[0]), "+f"((d)[1]), "+f"((d)[2]), "+f"((d)[3]) \
        : "r"((a)[0]), "r"((a)[1]), "r"((a)[2]), "r"((a)[3]), "r"(b0), "r"(b1))

__device__ __forceinline__ uint32_t f2tf32(float x) {
    uint32_t r;
    asm("cvt.rna.tf32.f32 %0, %1;" : "=r"(r) : "f"(x));
    return r;
}

// ---------------- smem geometry (XOR-swizzled, pitch = 128 B exact) ----------------
// Row = 32 floats = 8 chunks of 16 B. chunk' = chunk ^ (row & 7).
// Store: thread writes 16B chunks with the XOR applied.
// ldmatrix: 8 lanes address 8 consecutive rows at the same logical chunk ->
// physical chunks form a permutation of 0..7 -> conflict-free.
#define PITCH   128
#define TILE_B  (128 * PITCH)      // 16384 B
#define OFF_B   TILE_B
#define STAGE_B (2 * TILE_B)       // 32768 B
#define NSTG    3
#define SMEM_B  (NSTG * STAGE_B)   // 98304 B -> 2 CTAs/SM
#define BKC     32                 // K per chunk (4 k8 steps)

// ---------------------------------------------------------------------------
// C[M,N] = A[M,K] @ B[N,K]^T (+bias); A,B fp32 already tf32-rounded.
// 128x128 CTA tile, 8 warps (64x32 each), 3-stage cp.async, TF32 HMMA,
// 2 CTAs/SM.
// ---------------------------------------------------------------------------
__global__ __launch_bounds__(256, 2) void tf32_gemm(
    const float* __restrict__ A, const float* __restrict__ B,
    const float* __restrict__ bias, float* __restrict__ C,
    int M, int N, int K)
{
    extern __shared__ char sm[];
    const uint32_t sbase = smem_u32(sm);

    const int tid  = threadIdx.x;
    const int lane = tid & 31;
    const int wid  = tid >> 5;
    const int wm   = wid & 1;       // M half
    const int wn   = wid >> 1;      // N quarter
    const int bm   = blockIdx.y * 128;
    const int bn   = blockIdx.x * 128;

    // ---- loader mapping: 128 rows x 2 half-rows(64 B); 4 chunks/thread/tile ----
    const int lr   = tid >> 1;          // 0..127
    const int lh   = tid & 1;           // 0/1
    const float* gA = A + (size_t)(bm + lr) * K + lh * 16;
    const float* gB = B + (size_t)(bn + lr) * K + lh * 16;
    const int r7   = lr & 7;
    // swizzled 16B-chunk offsets for the 4 chunks this thread stores
    uint32_t sw[4];
    #pragma unroll
    for (int j = 0; j < 4; j++) sw[j] = (uint32_t)(((lh * 4 + j) ^ r7) << 4);
    const uint32_t sRowBase = (uint32_t)(lr * PITCH);

    // ---- ldmatrix lane addressing ----
    // every ldmatrix tile spans 8 consecutive rows -> row&7 == lane&7
    const int g   = lane >> 3;
    const int l8  = lane & 7;
    const int cA  = g >> 1;          // A: k 16B-half selector
    const int cB  = g & 1;           // B: k 16B-half selector
    const uint32_t aRow = (uint32_t)((wm * 64 + l8 + (g & 1) * 8) * PITCH);
    const uint32_t bRow = (uint32_t)((wn * 32 + l8 + (g >> 1) * 8) * PITCH);
    // per-k8-step swizzled chunk offsets
    uint32_t aSw[4], bSw[4];
    #pragma unroll
    for (int s = 0; s < 4; s++) {
        aSw[s] = (uint32_t)((((s * 2) + cA) ^ l8) << 4);
        bSw[s] = (uint32_t)((((s * 2) + cB) ^ l8) << 4);
    }

    float acc[4][4][4];
    #pragma unroll
    for (int i = 0; i < 4; i++)
        #pragma unroll
        for (int j = 0; j < 4; j++)
            #pragma unroll
            for (int q = 0; q < 4; q++) acc[i][j][q] = 0.0f;

    const int KC = K / BKC;

    auto issue = [&](int stg, int ko) {
        const uint32_t dA = sbase + (uint32_t)stg * STAGE_B + sRowBase;
        const uint32_t dB = dA + OFF_B;
        const float* sa = gA + ko;
        const float* sb = gB + ko;
        #pragma unroll
        for (int j = 0; j < 4; j++) {
            CP_ASYNC16(dA + sw[j], sa + j * 4);
            CP_ASYNC16(dB + sw[j], sb + j * 4);
        }
    };

    // prologue: 2 stages in flight
    issue(0, 0);   CP_COMMIT();
    issue(1, BKC); CP_COMMIT();

    uint32_t af[2][4][4], bf[2][2][4];

    for (int c = 0; c < KC; c++) {
        if (c == KC - 1) { CP_WAIT(0); } else { CP_WAIT(1); }
        __syncthreads();
        if (c + 2 < KC) { issue((c + 2) % NSTG, (c + 2) * BKC); CP_COMMIT(); }

        const uint32_t stg = sbase + (uint32_t)(c % NSTG) * STAGE_B;
        const uint32_t aB  = stg + aRow;
        const uint32_t bB  = stg + OFF_B + bRow;

        // frags for k8-step 0
        #pragma unroll
        for (int i = 0; i < 4; i++) LDSM4(af[0][i], aB + aSw[0] + (uint32_t)(i * 16 * PITCH));
        #pragma unroll
        for (int p = 0; p < 2; p++) LDSM4(bf[0][p], bB + bSw[0] + (uint32_t)(p * 16 * PITCH));

        #pragma unroll
        for (int s = 0; s < 4; s++) {
            const int cur = s & 1;
            if (s < 3) {
                const int nxt = cur ^ 1;
                #pragma unroll
                for (int i = 0; i < 4; i++)
                    LDSM4(af[nxt][i], aB + aSw[s + 1] + (uint32_t)(i * 16 * PITCH));
                #pragma unroll
                for (int p = 0; p < 2; p++)
                    LDSM4(bf[nxt][p], bB + bSw[s + 1] + (uint32_t)(p * 16 * PITCH));
            }
            #pragma unroll
            for (int i = 0; i < 4; i++) {
                #pragma unroll
                for (int j = 0; j < 4; j++) {
                    const int p = j >> 1, q = j & 1;
                    MMA_TF32(acc[i][j], af[cur][i], bf[cur][p][q * 2], bf[cur][p][q * 2 + 1]);
                }
            }
        }
    }

    // ---- epilogue ----
    #pragma unroll
    for (int i = 0; i < 4; i++) {
        const int row = bm + wm * 64 + i * 16 + (lane >> 2);
        #pragma unroll
        for (int j = 0; j < 4; j++) {
            const int col = bn + wn * 32 + j * 8 + (lane & 3) * 2;
            float b0 = 0.f, b1 = 0.f;
            if (bias) { b0 = bias[col]; b1 = bias[col + 1]; }
            float2 v0 = make_float2(acc[i][j][0] + b0, acc[i][j][1] + b1);
            float2 v1 = make_float2(acc[i][j][2] + b0, acc[i][j][3] + b1);
            *(float2*)(C + (size_t)row * N + col)       = v0;
            *(float2*)(C + (size_t)(row + 8) * N + col) = v1;
        }
    }
}

// ---------------------------------------------------------------------------
// fp32 -> tf32-rounded fp32 (cvt.rna)
// ---------------------------------------------------------------------------
__global__ __launch_bounds__(256) void round_tf32_kernel(
    const float* __restrict__ src, float* __restrict__ dst, int n4)
{
    const int i = blockIdx.x * blockDim.x + threadIdx.x;
    if (i >= n4) return;
    const float4 v = ((const float4*)src)[i];
    uint4 r;
    r.x = f2tf32(v.x); r.y = f2tf32(v.y);
    r.z = f2tf32(v.z); r.w = f2tf32(v.w);
    ((uint4*)dst)[i] = r;
}

// ---------------------------------------------------------------------------
// Per-token attention over heads (fp32), outputs tf32-rounded y.
// ---------------------------------------------------------------------------
__global__ __launch_bounds__(256) void attn_kernel(
    const float* __restrict__ qkv, float* __restrict__ y)
{
    __shared__ float sh[C3];
    __shared__ float att[16][16];

    const int token = blockIdx.x;
    const int tid   = threadIdx.x;
    const float* row = qkv + (size_t)token * C3;

    for (int i = tid; i < C3 / 4; i += 256)
        ((float4*)sh)[i] = ((const float4*)row)[i];
    __syncthreads();

    const int h = tid >> 4;
    const int gg = tid & 15;
    const float* qp = sh + h * 192;
    const float* kp = sh + gg * 192 + 64;

    float s = 0.0f;
    #pragma unroll
    for (int dd = 0; dd < 64; dd++) {
        int d = (dd + gg) & 63;
        s += qp[d] * kp[d];
    }
    att[h][gg] = s * 0.125f;
    __syncthreads();

    float m = -1e30f;
    #pragma unroll
    for (int j = 0; j < 16; j++) m = fmaxf(m, att[h][j]);
    float e = __expf(att[h][gg] - m);
    __syncthreads();
    att[h][gg] = e;
    __syncthreads();
    float denom = 0.0f;
    #pragma unroll
    for (int j = 0; j < 16; j++) denom += att[h][j];
    const float inv = 1.0f / denom;

    const int d0 = (tid & 15) * 4;
    float4 o = make_float4(0.f, 0.f, 0.f, 0.f);
    #pragma unroll
    for (int g2 = 0; g2 < 16; g2++) {
        const float w = att[h][g2];
        const float* vp = sh + g2 * 192 + 128 + d0;
        o.x += w * vp[0];
        o.y += w * vp[1];
        o.z += w * vp[2];
        o.w += w * vp[3];
    }
    uint4 r;
    r.x = f2tf32(o.x * inv);
    r.y = f2tf32(o.y * inv);
    r.z = f2tf32(o.z * inv);
    r.w = f2tf32(o.w * inv);
    *(uint4*)(y + (size_t)token * CDIM + h * 64 + d0) = r;
}

// ---------------------------------------------------------------------------
extern "C" void kernel_launch(void* const* d_in, const int* in_sizes, int n_in,
                              void* d_out, int out_size)
{
    const float* x    = (const float*)d_in[0];
    const float* Wqkv = (const float*)d_in[1];
    const float* Wout = (const float*)d_in[2];
    const float* bout = (const float*)d_in[3];
    float* out = (float*)d_out;

    float *qkv, *y, *xt, *w1t, *w2t;
    cudaGetSymbolAddress((void**)&qkv, g_qkv);
    cudaGetSymbolAddress((void**)&y,   g_y);
    cudaGetSymbolAddress((void**)&xt,  g_xt);
    cudaGetSymbolAddress((void**)&w1t, g_w1t);
    cudaGetSymbolAddress((void**)&w2t, g_w2t);

    cudaFuncSetAttribute(tf32_gemm, cudaFuncAttributeMaxDynamicSharedMemorySize, SMEM_B);

    // tf32 rounding passes (rna)
    round_tf32_kernel<<<(NTOK * CDIM / 4 + 255) / 256, 256>>>(x, xt, NTOK * CDIM / 4);
    round_tf32_kernel<<<(C3 * CDIM / 4 + 255) / 256, 256>>>(Wqkv, w1t, C3 * CDIM / 4);
    round_tf32_kernel<<<(CDIM * CDIM / 4 + 255) / 256, 256>>>(Wout, w2t, CDIM * CDIM / 4);

    // GEMM1: qkv = xt @ w1t^T   (16384 x 3072, K=1024)
    tf32_gemm<<<dim3(C3 / 128, NTOK / 128), 256, SMEM_B>>>(
        xt, w1t, nullptr, qkv, NTOK, C3, CDIM);

    // attention over heads (emits tf32-rounded y)
    attn_kernel<<<NTOK, 256>>>(qkv, y);

    // GEMM2: out = y @ w2t^T + bout   (16384 x 1024, K=1024)
    tf32_gemm<<<dim3(CDIM / 128, NTOK / 128), 256, SMEM_B>>>(
        y, w2t, bout, out, NTOK, CDIM, CDIM);
}